// round 16
// baseline (speedup 1.0000x reference)
#include <cuda_runtime.h>
#include <math.h>
#include <cstddef>

// B=256, T=64, D=16, S=64, H=128, O=8
#define NTHR 256
#define PREPT 256
#define QC 36     // cached k-pairs (72 k-rows) of this CTA's Wf3 n-half

// Pair-packed Wf3: g_Wf3P[(q*1024 + n)*2 + r] = Wf3[n*128 + 2*q + r]  (512 KB)
__device__ __align__(16) float g_Wf3P[64 * 1024 * 2];

__constant__ float cC[6]  = {0.0f, 0.161f, 0.327f, 0.9f, 0.9800255409045097f, 1.0f};
__constant__ float cBw[6] = {0.09646076681806523f, 0.01f, 0.4798896504144996f,
                             1.379008574103742f, -3.290069515436081f, 2.324710524099774f};
__constant__ float cA[6][5] = {
    {0.f, 0.f, 0.f, 0.f, 0.f},
    {0.161f, 0.f, 0.f, 0.f, 0.f},
    {-0.008480655492356989f, 0.335480655492357f, 0.f, 0.f, 0.f},
    {2.8971530571054935f, -6.359448489975075f, 4.3622954328695815f, 0.f, 0.f},
    {5.325864828439257f, -11.748883564062828f, 7.4955393428898365f, -0.09249506636175525f, 0.f},
    {5.86145544294642f, -12.92096931784711f, 8.159367898576159f, -0.071584973281401f,
     -0.028269050394068383f}};

struct __align__(16) Smem {
    float wc[QC * 512 * 2];    // cached Wf3 pairs [q][n_local][2]   147456 B
    float Wf2Q[32 * 128 * 4];  // [m][i][4]  (4 k per load)           65536 B
    float h2[4][128];          // all 4 rows, arrives ONLY via st.async 2048 B
    float h1[2][128];          // plain, 2 local rows                  1024 B
    float yj[2][64];           // plain, 2 local rows                   512 B
    float y[4][64];            //                                      1024 B
    float ks[6][4][64];        // arrives ONLY via st.async            6144 B
    float cbv[4][16];
    float ccv[4][16];
    float cdv[4][16];
    float bf1v[128];
    float bf2v[128];
    float bf3loc[512];
    unsigned long long h2_mbar;
    unsigned long long ks_mbar;
};

// ---------- helpers ----------
__device__ __forceinline__ unsigned long long fma2(unsigned long long a,
                                                   unsigned long long b,
                                                   unsigned long long c) {
    unsigned long long d;
    asm("fma.rn.f32x2 %0, %1, %2, %3;" : "=l"(d) : "l"(a), "l"(b), "l"(c));
    return d;
}
__device__ __forceinline__ float2 u2f(unsigned long long v) {
    float2 r;
    asm("mov.b64 {%0, %1}, %2;" : "=f"(r.x), "=f"(r.y) : "l"(v));
    return r;
}
__device__ __forceinline__ void ldg128(const float* p, unsigned long long& a,
                                       unsigned long long& b) {
    asm("ld.global.nc.v2.u64 {%0, %1}, [%2];" : "=l"(a), "=l"(b) : "l"(p));
}
__device__ __forceinline__ unsigned smem_u32(const void* p) {
    unsigned r;
    asm("{ .reg .u64 t; cvta.to.shared.u64 t, %1; cvt.u32.u64 %0, t; }"
        : "=r"(r) : "l"(p));
    return r;
}
__device__ __forceinline__ unsigned long long lds64(unsigned a) {
    unsigned long long v;
    asm("ld.shared.u64 %0, [%1];" : "=l"(v) : "r"(a));
    return v;
}
__device__ __forceinline__ float2 lds_f2(unsigned a) {
    float2 r;
    asm volatile("ld.shared.v2.f32 {%0, %1}, [%2];" : "=f"(r.x), "=f"(r.y) : "r"(a));
    return r;
}
// volatile: activation reads must stay after barriers / mbar waits
__device__ __forceinline__ void lds_v2u64(unsigned a, unsigned long long& x,
                                          unsigned long long& y) {
    asm volatile("ld.shared.v2.u64 {%0, %1}, [%2];" : "=l"(x), "=l"(y) : "r"(a));
}
__device__ __forceinline__ unsigned mapa_u32(unsigned laddr, unsigned peer) {
    unsigned r;
    asm("mapa.shared::cluster.u32 %0, %1, %2;" : "=r"(r) : "r"(laddr), "r"(peer));
    return r;
}
__device__ __forceinline__ void mbar_init(unsigned a, unsigned cnt) {
    asm volatile("mbarrier.init.shared.b64 [%0], %1;" :: "r"(a), "r"(cnt) : "memory");
}
__device__ __forceinline__ void mbar_expect_tx(unsigned a, unsigned bytes) {
    asm volatile("mbarrier.arrive.expect_tx.shared.b64 _, [%0], %1;"
                 :: "r"(a), "r"(bytes) : "memory");
}
__device__ __forceinline__ void mbar_wait(unsigned a, unsigned parity) {
    asm volatile(
        "{\n\t.reg .pred P;\n"
        "LW_%=:\n\t"
        "mbarrier.try_wait.parity.acquire.cta.shared::cta.b64 P, [%0], %1, 0x989680;\n\t"
        "@P bra LD_%=;\n\t"
        "bra LW_%=;\n"
        "LD_%=:\n\t}"
        :: "r"(a), "r"(parity) : "memory");
}
__device__ __forceinline__ void st_async32(unsigned dst, float v, unsigned mbar) {
    asm volatile("st.async.shared::cluster.mbarrier::complete_tx::bytes.b32 [%0], %1, [%2];"
                 :: "r"(dst), "f"(v), "r"(mbar) : "memory");
}
__device__ __forceinline__ float softplus_f(float x) {
    return fmaxf(x, 0.0f) + log1pf(__expf(-fabsf(x)));
}
__device__ __forceinline__ float tanh_fast(float x) {
    float e = __expf(2.0f * x);
    return 1.0f - 2.0f / (e + 1.0f);
}

__global__ void __launch_bounds__(PREPT, 1) prep_kernel(const float* __restrict__ Wf3) {
    int idx = blockIdx.x * PREPT + threadIdx.x;   // 512 x 256 = 131072
    int q = idx >> 11;
    int rem = idx & 2047;
    int n = rem >> 1;
    int r = rem & 1;
    g_Wf3P[idx] = Wf3[n * 128 + 2 * q + r];
}

__global__ void __launch_bounds__(NTHR, 1) __cluster_dims__(2, 1, 1) cde_kernel(
    const float* __restrict__ ts,
    const float* __restrict__ coeff_d, const float* __restrict__ coeff_c,
    const float* __restrict__ coeff_b, const float* __restrict__ coeff_a,
    const float* __restrict__ Wi1, const float* __restrict__ bi1,
    const float* __restrict__ Wi2, const float* __restrict__ bi2,
    const float* __restrict__ Wf1, const float* __restrict__ bf1,
    const float* __restrict__ Wf2, const float* __restrict__ bf2,
    const float* __restrict__ bf3,
    const float* __restrict__ Wr, const float* __restrict__ br,
    float* __restrict__ out)
{
    extern __shared__ char smraw[];
    Smem& sm = *reinterpret_cast<Smem*>(smraw);
    const int tid = threadIdx.x;
    unsigned rank;
    asm("mov.u32 %0, %%cluster_ctarank;" : "=r"(rank));
    const unsigned peer = rank ^ 1u;
    const int b0g = (blockIdx.x >> 1) * 4;

    const unsigned sbase = smem_u32(smraw);
    const unsigned off_h2 = (unsigned)offsetof(Smem, h2);
    const unsigned off_ks = (unsigned)offsetof(Smem, ks);
    const unsigned my_h2mbar = sbase + (unsigned)offsetof(Smem, h2_mbar);
    const unsigned my_ksmbar = sbase + (unsigned)offsetof(Smem, ks_mbar);
    const unsigned peer_h2mbar = mapa_u32(my_h2mbar, peer);
    const unsigned peer_ksmbar = mapa_u32(my_ksmbar, peer);
    const unsigned self_h2mbar = mapa_u32(my_h2mbar, rank);
    const unsigned self_ksmbar = mapa_u32(my_ksmbar, rank);
    const unsigned peer_h2base = mapa_u32(sbase + off_h2, peer);
    const unsigned peer_ksbase = mapa_u32(sbase + off_ks, peer);
    const unsigned self_h2base = mapa_u32(sbase + off_h2, rank);
    const unsigned self_ksbase = mapa_u32(sbase + off_ks, rank);

    if (tid == 0) { mbar_init(my_h2mbar, 1); mbar_init(my_ksmbar, 1); }

    // ---- one-time init ----
    // Wf2Q[(m*128+i)*4+c] = Wf2[i*128 + 4m + c]
    for (int idx = tid; idx < 32 * 128 * 4; idx += NTHR) {
        int m = idx >> 9, rem = idx & 511, i = rem >> 2, c = rem & 3;
        sm.Wf2Q[idx] = Wf2[i * 128 + 4 * m + c];
    }
    // wc[q][n_local][2] from g_Wf3P (this CTA's n-half)
    for (int idx = tid; idx < QC * 1024; idx += NTHR) {
        int q = idx >> 10, rem = idx & 1023;
        sm.wc[idx] = g_Wf3P[q * 2048 + rank * 1024 + rem];
    }
    if (tid < 128) { sm.bf1v[tid] = bf1[tid]; sm.bf2v[tid] = bf2[tid]; }
    for (int idx = tid; idx < 512; idx += NTHR) sm.bf3loc[idx] = bf3[rank * 512 + idx];
    __syncthreads();
    asm volatile("barrier.cluster.arrive.aligned;" ::: "memory");
    asm volatile("barrier.cluster.wait.aligned;" ::: "memory");

    // ---- y0 = softplus(x0 @ Wi1^T + bi1) @ Wi2^T + bi2  (h2/h1 as scratch) ----
    {
        if (tid < 64) {
            int b = tid >> 4, d = tid & 15;
            sm.cbv[b][d] = coeff_a[(b0g + b) * 63 * 16 + d];
        }
    }
    __syncthreads();
    {
        int b = tid >> 6;
        #pragma unroll
        for (int qq = 0; qq < 2; ++qq) {
            int jj = ((tid & 63) << 1) + qq;
            float acc = bi1[jj];
            #pragma unroll
            for (int d = 0; d < 16; ++d) acc += sm.cbv[b][d] * Wi1[jj * 16 + d];
            sm.h2[b][jj] = softplus_f(acc);
        }
    }
    __syncthreads();
    {
        int b = tid >> 6, s = tid & 63;
        float acc = bi2[s];
        #pragma unroll 8
        for (int k = 0; k < 128; ++k) acc += sm.h2[b][k] * Wi2[s * 128 + k];
        sm.y[b][s] = acc;
    }
    __syncthreads();
    if (tid < 16) {
        int bl = tid >> 3, o = tid & 7;
        int row = (int)rank * 2 + bl;
        float acc = br[o];
        #pragma unroll 8
        for (int s2 = 0; s2 < 64; ++s2) acc += sm.y[row][s2] * Wr[o * 64 + s2];
        out[((b0g + row) * 64 + 0) * 8 + o] = acc;
    }
    // h2 scratch use must be complete across the cluster before stage-0 async writes
    asm volatile("barrier.cluster.arrive.aligned;" ::: "memory");
    asm volatile("barrier.cluster.wait.aligned;" ::: "memory");

    // per-thread constants
    const int bl14 = tid >> 7;          // GEMM1: local row 0/1
    const int i14  = tid & 127;         // GEMM1: output index
    const unsigned yj_b  = sbase + (unsigned)offsetof(Smem, yj) + (unsigned)bl14 * 256u;
    const unsigned h1_0  = sbase + (unsigned)offsetof(Smem, h1);
    const unsigned h2b   = sbase + off_h2;                         // + row*512 + q*8
    const unsigned wcb   = sbase + (unsigned)offsetof(Smem, wc) + (unsigned)tid * 16u;
    const float* gW = g_Wf3P + (rank * 512 + 2 * tid) * 2;         // + q*2048 floats
    const int d0  = (tid & 7) << 1;
    const int s_g = (int)rank * 32 + (tid >> 3);
    const bool writer = ((tid & 7) == 0);
    const unsigned cb_a = sbase + (unsigned)offsetof(Smem, cbv) + (unsigned)d0 * 4u;
    const unsigned cc_a = sbase + (unsigned)offsetof(Smem, ccv) + (unsigned)d0 * 4u;
    const unsigned cd_a = sbase + (unsigned)offsetof(Smem, cdv) + (unsigned)d0 * 4u;

    // GEMM2 k-split constants: thread = (i2 = tid>>1, kh2 = tid&1)
    const int i2  = tid >> 1;
    const int kh2 = tid & 1;
    const unsigned w2q = sbase + (unsigned)offsetof(Smem, Wf2Q)
                       + (unsigned)kh2 * (16u * 2048u) + (unsigned)i2 * 16u;
    const unsigned h1a = h1_0 + (unsigned)kh2 * 256u;   // m base = kh2*16, *16B

    // GEMM1 weights: loaded ONCE into permanent registers (constant data).
    unsigned long long w1r[32];
    {
        const float* w1p = Wf1 + i14 * 64;
        #pragma unroll
        for (int m = 0; m < 16; ++m) ldg128(w1p + 4 * m, w1r[2 * m], w1r[2 * m + 1]);
    }

    unsigned ph = 0;

    // ---- time loop: 63 steps x 6 RK stages ----
    for (int t = 0; t < 63; ++t) {
        float h = ts[t + 1] - ts[t];
        if (tid < 64) {
            int b = tid >> 4, d = tid & 15;
            int base = ((b0g + b) * 63 + t) * 16 + d;
            sm.cbv[b][d] = coeff_b[base];
            sm.ccv[b][d] = coeff_c[base];
            sm.cdv[b][d] = coeff_d[base];
        }

        #pragma unroll 1
        for (int j = 0; j < 6; ++j) {
            if (tid == 0) {
                mbar_expect_tx(my_h2mbar, 2048u);   // self 1024 + peer 1024
                mbar_expect_tx(my_ksmbar, 1024u);   // self 512 + peer 512
            }
            if (tid < 128) {  // yj for 2 local rows (plain float)
                int bl = tid >> 6, s = tid & 63;
                int row = (int)rank * 2 + bl;
                float v = sm.y[row][s];
                #pragma unroll
                for (int m = 0; m < 5; ++m)
                    if (m < j) v += h * cA[j][m] * sm.ks[m][row][s];
                sm.yj[bl][s] = v;
            }

            // prefetch 2 streamed Wf3 batches (hides under GEMM1/2 + barriers)
            unsigned long long wvA[8], wvB[8];
            #define G3_ISSUE(WV, B)                                                   \
                {                                                                     \
                    const float* gq = gW + (QC + 4 * (B)) * 2048;                     \
                    _Pragma("unroll")                                                 \
                    for (int m = 0; m < 4; ++m)                                       \
                        ldg128(gq + m * 2048, (WV)[2 * m], (WV)[2 * m + 1]);          \
                }
            G3_ISSUE(wvA, 0)
            G3_ISSUE(wvB, 1)

            __syncthreads();  // S1

            // GEMM1: all 256 threads; output (bl14, i14); K=64 = 32 q, weights in regs
            {
                unsigned long long acc0 = 0ull, acc1 = 0ull;
                #pragma unroll
                for (int qp = 0; qp < 16; ++qp) {
                    unsigned long long hx, hy;
                    lds_v2u64(yj_b + (unsigned)qp * 16u, hx, hy);
                    acc0 = fma2(hx, w1r[2 * qp], acc0);
                    acc1 = fma2(hy, w1r[2 * qp + 1], acc1);
                }
                float2 f0 = u2f(acc0), f1 = u2f(acc1);
                sm.h1[bl14][i14] = softplus_f((f0.x + f0.y) + (f1.x + f1.y) + sm.bf1v[i14]);
            }
            __syncthreads();  // S2

            // GEMM2: ALL 256 threads; thread (i2, kh2) does its 16-m k-half for BOTH
            // rows; combine across kh via shfl_xor(1); kh2==0 sends via st.async only.
            {
                unsigned long long r0a0 = 0ull, r0a1 = 0ull, r1a0 = 0ull, r1a1 = 0ull;
                #pragma unroll
                for (int m = 0; m < 16; ++m) {
                    unsigned long long w0, w1;
                    lds_v2u64(w2q + (unsigned)m * 2048u, w0, w1);
                    unsigned long long h0x, h0y, h1x, h1y;
                    lds_v2u64(h1a +          (unsigned)m * 16u, h0x, h0y);
                    lds_v2u64(h1a + 512u +   (unsigned)m * 16u, h1x, h1y);
                    r0a0 = fma2(h0x, w0, r0a0); r0a1 = fma2(h0y, w1, r0a1);
                    r1a0 = fma2(h1x, w0, r1a0); r1a1 = fma2(h1y, w1, r1a1);
                }
                float2 f0 = u2f(r0a0), f1 = u2f(r0a1);
                float s0 = (f0.x + f0.y) + (f1.x + f1.y);
                f0 = u2f(r1a0); f1 = u2f(r1a1);
                float s1 = (f0.x + f0.y) + (f1.x + f1.y);
                s0 += __shfl_xor_sync(0xffffffffu, s0, 1);
                s1 += __shfl_xor_sync(0xffffffffu, s1, 1);
                if (!kh2) {
                    float bz = sm.bf2v[i2];
                    float v0 = softplus_f(s0 + bz);
                    float v1 = softplus_f(s1 + bz);
                    int row0 = (int)rank * 2;
                    unsigned doff0 = (unsigned)(row0 * 128 + i2) * 4u;
                    unsigned doff1 = (unsigned)((row0 + 1) * 128 + i2) * 4u;
                    st_async32(self_h2base + doff0, v0, self_h2mbar);
                    st_async32(peer_h2base + doff0, v0, peer_h2mbar);
                    st_async32(self_h2base + doff1, v1, self_h2mbar);
                    st_async32(peer_h2base + doff1, v1, peer_h2mbar);
                }
            }
            mbar_wait(my_h2mbar, ph);   // ALL h2 rows arrived (acquire)

            // GEMM3: thread owns n0=2tid, n0+1 (local), 4 rows; K=128 = 64 q
            unsigned long long a00 = 0, a01 = 0, a10 = 0, a11 = 0;
            unsigned long long a20 = 0, a21 = 0, a30 = 0, a31 = 0;
            #define G3_STEP(HX, HY, W00, W01, W10, W11, R0, R1)                       \
                {                                                                     \
                    R0 = fma2(HX, W00, R0); R0 = fma2(HY, W10, R0);                   \
                    R1 = fma2(HX, W01, R1); R1 = fma2(HY, W11, R1);                   \
                }
            #define G3_CACHED(Q0, Q1)                                                 \
                {                                                                     \
                    _Pragma("unroll")                                                 \
                    for (int q = (Q0); q < (Q1); q += 2) {                            \
                        unsigned long long w00, w01, w10, w11;                        \
                        lds_v2u64(wcb + (unsigned)q * 4096u, w00, w01);               \
                        lds_v2u64(wcb + (unsigned)(q + 1) * 4096u, w10, w11);         \
                        unsigned long long h0x, h0y, h1x, h1y, h2x, h2y, h3x, h3y;    \
                        lds_v2u64(h2b +           (unsigned)q * 8u, h0x, h0y);        \
                        lds_v2u64(h2b + 512u  +   (unsigned)q * 8u, h1x, h1y);        \
                        lds_v2u64(h2b + 1024u +   (unsigned)q * 8u, h2x, h2y);        \
                        lds_v2u64(h2b + 1536u +   (unsigned)q * 8u, h3x, h3y);        \
                        G3_STEP(h0x, h0y, w00, w01, w10, w11, a00, a01)               \
                        G3_STEP(h1x, h1y, w00, w01, w10, w11, a10, a11)               \
                        G3_STEP(h2x, h2y, w00, w01, w10, w11, a20, a21)               \
                        G3_STEP(h3x, h3y, w00, w01, w10, w11, a30, a31)               \
                    }                                                                 \
                }
            #define G3_CONSUME(WV, B)                                                 \
                {                                                                     \
                    _Pragma("unroll")                                                 \
                    for (int jj = 0; jj < 2; ++jj) {                                  \
                        int q = QC + 4 * (B) + 2 * jj;                                \
                        unsigned long long h0x, h0y, h1x, h1y, h2x, h2y, h3x, h3y;    \
                        lds_v2u64(h2b +           (unsigned)q * 8u, h0x, h0y);        \
                        lds_v2u64(h2b + 512u  +   (unsigned)q * 8u, h1x, h1y);        \
                        lds_v2u64(h2b + 1024u +   (unsigned)q * 8u, h2x, h2y);        \
                        lds_v2u64(h2b + 1536u +   (unsigned)q * 8u, h3x, h3y);        \
                        unsigned long long w00 = (WV)[4 * jj],     w01 = (WV)[4 * jj + 1]; \
                        unsigned long long w10 = (WV)[4 * jj + 2], w11 = (WV)[4 * jj + 3]; \
                        G3_STEP(h0x, h0y, w00, w01, w10, w11, a00, a01)               \
                        G3_STEP(h1x, h1y, w00, w01, w10, w11, a10, a11)               \
                        G3_STEP(h2x, h2y, w00, w01, w10, w11, a20, a21)               \
                        G3_STEP(h3x, h3y, w00, w01, w10, w11, a30, a31)               \
                    }                                                                 \
                }
            // schedule: 7 streamed batches (q=36..63), pipeline depth 2
            G3_CACHED(0, 18)
            G3_CONSUME(wvA, 0)  G3_ISSUE(wvA, 2)
            G3_CACHED(18, QC)
            G3_CONSUME(wvB, 1)  G3_ISSUE(wvB, 3)
            G3_CONSUME(wvA, 2)  G3_ISSUE(wvA, 4)
            G3_CONSUME(wvB, 3)  G3_ISSUE(wvB, 5)
            G3_CONSUME(wvA, 4)  G3_ISSUE(wvA, 6)
            G3_CONSUME(wvB, 5)
            G3_CONSUME(wvA, 6)

            // epilogue: fold k-parity, dx computed inline, tanh, einsum partial,
            // 8-lane reduce; ks goes out ONLY via st.async -> no S4
            float z0 = sm.bf3loc[2 * tid], z1 = sm.bf3loc[2 * tid + 1];
            float fr = cC[j] * h;
            float kv[4];
            {
                unsigned long long aa0[4] = {a00, a10, a20, a30};
                unsigned long long aa1[4] = {a01, a11, a21, a31};
                #pragma unroll
                for (int b = 0; b < 4; ++b) {
                    float2 cb = lds_f2(cb_a + (unsigned)b * 64u);
                    float2 cc = lds_f2(cc_a + (unsigned)b * 64u);
                    float2 cd = lds_f2(cd_a + (unsigned)b * 64u);
                    float dx0 = cb.x + fr * (2.0f * cc.x + 3.0f * fr * cd.x);
                    float dx1 = cb.y + fr * (2.0f * cc.y + 3.0f * fr * cd.y);
                    float2 f0 = u2f(aa0[b]);
                    float2 f1 = u2f(aa1[b]);
                    float v0 = tanh_fast(f0.x + f0.y + z0);
                    float v1 = tanh_fast(f1.x + f1.y + z1);
                    float p = v0 * dx0 + v1 * dx1;
                    p += __shfl_xor_sync(0xffffffffu, p, 1);
                    p += __shfl_xor_sync(0xffffffffu, p, 2);
                    p += __shfl_xor_sync(0xffffffffu, p, 4);
                    kv[b] = p;
                }
            }
            if (writer) {
                #pragma unroll
                for (int b = 0; b < 4; ++b) {
                    unsigned doff = (unsigned)(((j * 4 + b) * 64) + s_g) * 4u;
                    st_async32(self_ksbase + doff, kv[b], self_ksmbar);
                    st_async32(peer_ksbase + doff, kv[b], peer_ksmbar);
                }
            }
            mbar_wait(my_ksmbar, ph);  // full ks stage row set arrived (acquire)
            ph ^= 1;
        }

        {  // y += h * sum_j B_SOL[j] * ks[j]
            int b = tid >> 6, s = tid & 63;
            float sum = 0.0f;
            #pragma unroll
            for (int j = 0; j < 6; ++j) sum += cBw[j] * sm.ks[j][b][s];
            sm.y[b][s] += h * sum;
        }
        __syncthreads();  // S5

        if (tid < 16) {  // out[:, t+1, :] for 2 local rows
            int bl = tid >> 3, o = tid & 7;
            int row = (int)rank * 2 + bl;
            float acc = br[o];
            #pragma unroll 8
            for (int s2 = 0; s2 < 64; ++s2) acc += sm.y[row][s2] * Wr[o * 64 + s2];
            out[((b0g + row) * 64 + (t + 1)) * 8 + o] = acc;
        }
    }
}

extern "C" void kernel_launch(void* const* d_in, const int* in_sizes, int n_in,
                              void* d_out, int out_size) {
    const float* ts      = (const float*)d_in[0];
    const float* coeff_d = (const float*)d_in[1];
    const float* coeff_c = (const float*)d_in[2];
    const float* coeff_b = (const float*)d_in[3];
    const float* coeff_a = (const float*)d_in[4];
    const float* Wi1 = (const float*)d_in[5];
    const float* bi1 = (const float*)d_in[6];
    const float* Wi2 = (const float*)d_in[7];
    const float* bi2 = (const float*)d_in[8];
    const float* Wf1 = (const float*)d_in[9];
    const float* bf1 = (const float*)d_in[10];
    const float* Wf2 = (const float*)d_in[11];
    const float* bf2 = (const float*)d_in[12];
    const float* Wf3 = (const float*)d_in[13];
    const float* bf3 = (const float*)d_in[14];
    const float* Wr  = (const float*)d_in[15];
    const float* br  = (const float*)d_in[16];
    float* out = (float*)d_out;

    cudaFuncSetAttribute(cde_kernel, cudaFuncAttributeMaxDynamicSharedMemorySize,
                         (int)sizeof(Smem));

    prep_kernel<<<512, PREPT>>>(Wf3);
    cde_kernel<<<128, NTHR, sizeof(Smem)>>>(ts, coeff_d, coeff_c, coeff_b, coeff_a,
                                            Wi1, bi1, Wi2, bi2, Wf1, bf1, Wf2, bf2,
                                            bf3, Wr, br, out);
}

// round 17
// speedup vs baseline: 1.1278x; 1.1278x over previous
#include <cuda_runtime.h>
#include <math.h>
#include <cstddef>

// B=256, T=64, D=16, S=64, H=128, O=8
#define NTHR 256
#define PREPT 256
#define QC 36     // cached k-pairs (72 k-rows) of this CTA's Wf3 n-half

// Pair-packed Wf3: g_Wf3P[(q*1024 + n)*2 + r] = Wf3[n*128 + 2*q + r]  (512 KB)
__device__ __align__(16) float g_Wf3P[64 * 1024 * 2];

__constant__ float cC[6]  = {0.0f, 0.161f, 0.327f, 0.9f, 0.9800255409045097f, 1.0f};
__constant__ float cBw[6] = {0.09646076681806523f, 0.01f, 0.4798896504144996f,
                             1.379008574103742f, -3.290069515436081f, 2.324710524099774f};
__constant__ float cA[6][5] = {
    {0.f, 0.f, 0.f, 0.f, 0.f},
    {0.161f, 0.f, 0.f, 0.f, 0.f},
    {-0.008480655492356989f, 0.335480655492357f, 0.f, 0.f, 0.f},
    {2.8971530571054935f, -6.359448489975075f, 4.3622954328695815f, 0.f, 0.f},
    {5.325864828439257f, -11.748883564062828f, 7.4955393428898365f, -0.09249506636175525f, 0.f},
    {5.86145544294642f, -12.92096931784711f, 8.159367898576159f, -0.071584973281401f,
     -0.028269050394068383f}};

struct __align__(16) Smem {
    float wc[QC * 512 * 2];    // cached Wf3 pairs [q][n_local][2]   147456 B
    float Wf2Q[32 * 128 * 4];  // [m][i][4]  (4 k per load)           65536 B
    float h2[4][128];          // all 4 rows, arrives ONLY via st.async 2048 B
    float h1[2][128];          // plain, 2 local rows                  1024 B
    float yj[2][64];           // plain, 2 local rows                   512 B
    float y[4][64];            //                                      1024 B
    float ks[6][4][64];        // arrives ONLY via st.async            6144 B
    float cbv[4][16];
    float ccv[4][16];
    float cdv[4][16];
    float bf1v[128];
    float bf2v[128];
    float bf3loc[512];
    unsigned long long h2_mbar;
    unsigned long long ks_mbar;
};

// ---------- helpers ----------
__device__ __forceinline__ unsigned long long fma2(unsigned long long a,
                                                   unsigned long long b,
                                                   unsigned long long c) {
    unsigned long long d;
    asm("fma.rn.f32x2 %0, %1, %2, %3;" : "=l"(d) : "l"(a), "l"(b), "l"(c));
    return d;
}
__device__ __forceinline__ float2 u2f(unsigned long long v) {
    float2 r;
    asm("mov.b64 {%0, %1}, %2;" : "=f"(r.x), "=f"(r.y) : "l"(v));
    return r;
}
__device__ __forceinline__ void ldg128(const float* p, unsigned long long& a,
                                       unsigned long long& b) {
    asm("ld.global.nc.v2.u64 {%0, %1}, [%2];" : "=l"(a), "=l"(b) : "l"(p));
}
__device__ __forceinline__ unsigned smem_u32(const void* p) {
    unsigned r;
    asm("{ .reg .u64 t; cvta.to.shared.u64 t, %1; cvt.u32.u64 %0, t; }"
        : "=r"(r) : "l"(p));
    return r;
}
__device__ __forceinline__ unsigned long long lds64(unsigned a) {
    unsigned long long v;
    asm("ld.shared.u64 %0, [%1];" : "=l"(v) : "r"(a));
    return v;
}
__device__ __forceinline__ float2 lds_f2(unsigned a) {
    float2 r;
    asm volatile("ld.shared.v2.f32 {%0, %1}, [%2];" : "=f"(r.x), "=f"(r.y) : "r"(a));
    return r;
}
// volatile: activation reads must stay after barriers / mbar waits
__device__ __forceinline__ void lds_v2u64(unsigned a, unsigned long long& x,
                                          unsigned long long& y) {
    asm volatile("ld.shared.v2.u64 {%0, %1}, [%2];" : "=l"(x), "=l"(y) : "r"(a));
}
__device__ __forceinline__ unsigned mapa_u32(unsigned laddr, unsigned peer) {
    unsigned r;
    asm("mapa.shared::cluster.u32 %0, %1, %2;" : "=r"(r) : "r"(laddr), "r"(peer));
    return r;
}
__device__ __forceinline__ void mbar_init(unsigned a, unsigned cnt) {
    asm volatile("mbarrier.init.shared.b64 [%0], %1;" :: "r"(a), "r"(cnt) : "memory");
}
__device__ __forceinline__ void mbar_expect_tx(unsigned a, unsigned bytes) {
    asm volatile("mbarrier.arrive.expect_tx.shared.b64 _, [%0], %1;"
                 :: "r"(a), "r"(bytes) : "memory");
}
__device__ __forceinline__ void mbar_wait(unsigned a, unsigned parity) {
    asm volatile(
        "{\n\t.reg .pred P;\n"
        "LW_%=:\n\t"
        "mbarrier.try_wait.parity.acquire.cta.shared::cta.b64 P, [%0], %1, 0x989680;\n\t"
        "@P bra LD_%=;\n\t"
        "bra LW_%=;\n"
        "LD_%=:\n\t}"
        :: "r"(a), "r"(parity) : "memory");
}
__device__ __forceinline__ void st_async32(unsigned dst, float v, unsigned mbar) {
    asm volatile("st.async.shared::cluster.mbarrier::complete_tx::bytes.b32 [%0], %1, [%2];"
                 :: "r"(dst), "f"(v), "r"(mbar) : "memory");
}
__device__ __forceinline__ float softplus_f(float x) {
    return fmaxf(x, 0.0f) + log1pf(__expf(-fabsf(x)));
}
__device__ __forceinline__ float tanh_fast(float x) {
    float e = __expf(2.0f * x);
    return 1.0f - 2.0f / (e + 1.0f);
}

__global__ void __launch_bounds__(PREPT, 1) prep_kernel(const float* __restrict__ Wf3) {
    int idx = blockIdx.x * PREPT + threadIdx.x;   // 512 x 256 = 131072
    int q = idx >> 11;
    int rem = idx & 2047;
    int n = rem >> 1;
    int r = rem & 1;
    g_Wf3P[idx] = Wf3[n * 128 + 2 * q + r];
}

__global__ void __launch_bounds__(NTHR, 1) __cluster_dims__(2, 1, 1) cde_kernel(
    const float* __restrict__ ts,
    const float* __restrict__ coeff_d, const float* __restrict__ coeff_c,
    const float* __restrict__ coeff_b, const float* __restrict__ coeff_a,
    const float* __restrict__ Wi1, const float* __restrict__ bi1,
    const float* __restrict__ Wi2, const float* __restrict__ bi2,
    const float* __restrict__ Wf1, const float* __restrict__ bf1,
    const float* __restrict__ Wf2, const float* __restrict__ bf2,
    const float* __restrict__ bf3,
    const float* __restrict__ Wr, const float* __restrict__ br,
    float* __restrict__ out)
{
    extern __shared__ char smraw[];
    Smem& sm = *reinterpret_cast<Smem*>(smraw);
    const int tid = threadIdx.x;
    unsigned rank;
    asm("mov.u32 %0, %%cluster_ctarank;" : "=r"(rank));
    const unsigned peer = rank ^ 1u;
    const int b0g = (blockIdx.x >> 1) * 4;

    const unsigned sbase = smem_u32(smraw);
    const unsigned off_h2 = (unsigned)offsetof(Smem, h2);
    const unsigned off_ks = (unsigned)offsetof(Smem, ks);
    const unsigned my_h2mbar = sbase + (unsigned)offsetof(Smem, h2_mbar);
    const unsigned my_ksmbar = sbase + (unsigned)offsetof(Smem, ks_mbar);
    const unsigned peer_h2mbar = mapa_u32(my_h2mbar, peer);
    const unsigned peer_ksmbar = mapa_u32(my_ksmbar, peer);
    const unsigned self_h2mbar = mapa_u32(my_h2mbar, rank);
    const unsigned self_ksmbar = mapa_u32(my_ksmbar, rank);
    const unsigned peer_h2base = mapa_u32(sbase + off_h2, peer);
    const unsigned peer_ksbase = mapa_u32(sbase + off_ks, peer);
    const unsigned self_h2base = mapa_u32(sbase + off_h2, rank);
    const unsigned self_ksbase = mapa_u32(sbase + off_ks, rank);

    if (tid == 0) { mbar_init(my_h2mbar, 1); mbar_init(my_ksmbar, 1); }

    // ---- one-time init ----
    // Wf2Q[(m*128+i)*4+c] = Wf2[i*128 + 4m + c]
    for (int idx = tid; idx < 32 * 128 * 4; idx += NTHR) {
        int m = idx >> 9, rem = idx & 511, i = rem >> 2, c = rem & 3;
        sm.Wf2Q[idx] = Wf2[i * 128 + 4 * m + c];
    }
    // wc[q][n_local][2] from g_Wf3P (this CTA's n-half)
    for (int idx = tid; idx < QC * 1024; idx += NTHR) {
        int q = idx >> 10, rem = idx & 1023;
        sm.wc[idx] = g_Wf3P[q * 2048 + rank * 1024 + rem];
    }
    if (tid < 128) { sm.bf1v[tid] = bf1[tid]; sm.bf2v[tid] = bf2[tid]; }
    for (int idx = tid; idx < 512; idx += NTHR) sm.bf3loc[idx] = bf3[rank * 512 + idx];
    __syncthreads();
    asm volatile("barrier.cluster.arrive.aligned;" ::: "memory");
    asm volatile("barrier.cluster.wait.aligned;" ::: "memory");

    // ---- y0 = softplus(x0 @ Wi1^T + bi1) @ Wi2^T + bi2  (h2/h1 as scratch) ----
    {
        if (tid < 64) {
            int b = tid >> 4, d = tid & 15;
            sm.cbv[b][d] = coeff_a[(b0g + b) * 63 * 16 + d];
        }
    }
    __syncthreads();
    {
        int b = tid >> 6;
        #pragma unroll
        for (int qq = 0; qq < 2; ++qq) {
            int jj = ((tid & 63) << 1) + qq;
            float acc = bi1[jj];
            #pragma unroll
            for (int d = 0; d < 16; ++d) acc += sm.cbv[b][d] * Wi1[jj * 16 + d];
            sm.h2[b][jj] = softplus_f(acc);
        }
    }
    __syncthreads();
    {
        int b = tid >> 6, s = tid & 63;
        float acc = bi2[s];
        #pragma unroll 8
        for (int k = 0; k < 128; ++k) acc += sm.h2[b][k] * Wi2[s * 128 + k];
        sm.y[b][s] = acc;
    }
    __syncthreads();
    if (tid < 16) {
        int bl = tid >> 3, o = tid & 7;
        int row = (int)rank * 2 + bl;
        float acc = br[o];
        #pragma unroll 8
        for (int s2 = 0; s2 < 64; ++s2) acc += sm.y[row][s2] * Wr[o * 64 + s2];
        out[((b0g + row) * 64 + 0) * 8 + o] = acc;
    }
    // h2 scratch use must be complete across the cluster before stage-0 async writes
    asm volatile("barrier.cluster.arrive.aligned;" ::: "memory");
    asm volatile("barrier.cluster.wait.aligned;" ::: "memory");

    // per-thread constants
    const int bl14 = tid >> 7;          // GEMM1: local row 0/1
    const int i14  = tid & 127;         // GEMM1: output index
    const unsigned yj_b  = sbase + (unsigned)offsetof(Smem, yj) + (unsigned)bl14 * 256u;
    const unsigned h1_0  = sbase + (unsigned)offsetof(Smem, h1);
    const unsigned w2q_i = sbase + (unsigned)offsetof(Smem, Wf2Q) + (unsigned)tid * 16u;
    const unsigned h2b   = sbase + off_h2;                         // + row*512 + q*8
    const unsigned wcb   = sbase + (unsigned)offsetof(Smem, wc) + (unsigned)tid * 16u;
    const float* gW = g_Wf3P + (rank * 512 + 2 * tid) * 2;         // + q*2048 floats
    const int d0  = (tid & 7) << 1;
    const int s_g = (int)rank * 32 + (tid >> 3);
    const bool writer = ((tid & 7) == 0);
    const unsigned cb_a = sbase + (unsigned)offsetof(Smem, cbv) + (unsigned)d0 * 4u;
    const unsigned cc_a = sbase + (unsigned)offsetof(Smem, ccv) + (unsigned)d0 * 4u;
    const unsigned cd_a = sbase + (unsigned)offsetof(Smem, cdv) + (unsigned)d0 * 4u;

    // GEMM1 weights: loaded ONCE into permanent registers (constant data).
    unsigned long long w1r[32];
    {
        const float* w1p = Wf1 + i14 * 64;
        #pragma unroll
        for (int m = 0; m < 16; ++m) ldg128(w1p + 4 * m, w1r[2 * m], w1r[2 * m + 1]);
    }

    unsigned ph = 0;

    // ---- time loop: 63 steps x 6 RK stages ----
    for (int t = 0; t < 63; ++t) {
        float h = ts[t + 1] - ts[t];
        if (tid < 64) {
            int b = tid >> 4, d = tid & 15;
            int base = ((b0g + b) * 63 + t) * 16 + d;
            sm.cbv[b][d] = coeff_b[base];
            sm.ccv[b][d] = coeff_c[base];
            sm.cdv[b][d] = coeff_d[base];
        }

        #pragma unroll 1
        for (int j = 0; j < 6; ++j) {
            if (tid == 0) {
                mbar_expect_tx(my_h2mbar, 2048u);   // self 1024 + peer 1024
                mbar_expect_tx(my_ksmbar, 1024u);   // self 512 + peer 512
            }
            if (tid < 128) {  // yj for 2 local rows (plain float)
                int bl = tid >> 6, s = tid & 63;
                int row = (int)rank * 2 + bl;
                float v = sm.y[row][s];
                #pragma unroll
                for (int m = 0; m < 5; ++m)
                    if (m < j) v += h * cA[j][m] * sm.ks[m][row][s];
                sm.yj[bl][s] = v;
            }

            // prefetch 2 streamed Wf3 batches (hides under GEMM1/2 + barriers)
            unsigned long long wvA[8], wvB[8];
            #define G3_ISSUE(WV, B)                                                   \
                {                                                                     \
                    const float* gq = gW + (QC + 4 * (B)) * 2048;                     \
                    _Pragma("unroll")                                                 \
                    for (int m = 0; m < 4; ++m)                                       \
                        ldg128(gq + m * 2048, (WV)[2 * m], (WV)[2 * m + 1]);          \
                }
            G3_ISSUE(wvA, 0)
            G3_ISSUE(wvB, 1)

            __syncthreads();  // S1

            // GEMM1: all 256 threads; output (bl14, i14); K=64 = 32 q, weights in regs
            {
                unsigned long long acc0 = 0ull, acc1 = 0ull;
                #pragma unroll
                for (int qp = 0; qp < 16; ++qp) {
                    unsigned long long hx, hy;
                    lds_v2u64(yj_b + (unsigned)qp * 16u, hx, hy);
                    acc0 = fma2(hx, w1r[2 * qp], acc0);
                    acc1 = fma2(hy, w1r[2 * qp + 1], acc1);
                }
                float2 f0 = u2f(acc0), f1 = u2f(acc1);
                sm.h1[bl14][i14] = softplus_f((f0.x + f0.y) + (f1.x + f1.y) + sm.bf1v[i14]);
            }

            // GEMM2 weight preload for m=0,1 (constant data; hides LDS latency across S2)
            unsigned long long g2w0 = 0ull, g2w1 = 0ull, g2w2 = 0ull, g2w3 = 0ull;
            if (tid < 128) {
                lds_v2u64(w2q_i, g2w0, g2w1);
                lds_v2u64(w2q_i + 2048u, g2w2, g2w3);
            }
            __syncthreads();  // S2

            // GEMM2: 128 threads; thread = i, computes BOTH rows with ONE weight stream.
            // Results go out ONLY via st.async (self + peer) -> no S3 needed.
            if (tid < 128) {
                unsigned long long r0a0 = 0ull, r0a1 = 0ull, r1a0 = 0ull, r1a1 = 0ull;
                {   // m = 0 (preloaded weights)
                    unsigned long long h0x, h0y, h1x, h1y;
                    lds_v2u64(h1_0, h0x, h0y);
                    lds_v2u64(h1_0 + 512u, h1x, h1y);
                    r0a0 = fma2(h0x, g2w0, r0a0); r0a1 = fma2(h0y, g2w1, r0a1);
                    r1a0 = fma2(h1x, g2w0, r1a0); r1a1 = fma2(h1y, g2w1, r1a1);
                }
                {   // m = 1 (preloaded weights)
                    unsigned long long h0x, h0y, h1x, h1y;
                    lds_v2u64(h1_0 + 16u, h0x, h0y);
                    lds_v2u64(h1_0 + 512u + 16u, h1x, h1y);
                    r0a0 = fma2(h0x, g2w2, r0a0); r0a1 = fma2(h0y, g2w3, r0a1);
                    r1a0 = fma2(h1x, g2w2, r1a0); r1a1 = fma2(h1y, g2w3, r1a1);
                }
                #pragma unroll
                for (int m = 2; m < 32; ++m) {
                    unsigned long long w0, w1;
                    lds_v2u64(w2q_i + (unsigned)m * 2048u, w0, w1);
                    unsigned long long h0x, h0y, h1x, h1y;
                    lds_v2u64(h1_0 +          (unsigned)m * 16u, h0x, h0y);
                    lds_v2u64(h1_0 + 512u +   (unsigned)m * 16u, h1x, h1y);
                    r0a0 = fma2(h0x, w0, r0a0); r0a1 = fma2(h0y, w1, r0a1);
                    r1a0 = fma2(h1x, w0, r1a0); r1a1 = fma2(h1y, w1, r1a1);
                }
                float bz = sm.bf2v[tid];
                float2 f0 = u2f(r0a0), f1 = u2f(r0a1);
                float v0 = softplus_f((f0.x + f0.y) + (f1.x + f1.y) + bz);
                f0 = u2f(r1a0); f1 = u2f(r1a1);
                float v1 = softplus_f((f0.x + f0.y) + (f1.x + f1.y) + bz);
                int row0 = (int)rank * 2;
                unsigned doff0 = (unsigned)(row0 * 128 + tid) * 4u;
                unsigned doff1 = (unsigned)((row0 + 1) * 128 + tid) * 4u;
                st_async32(self_h2base + doff0, v0, self_h2mbar);
                st_async32(peer_h2base + doff0, v0, peer_h2mbar);
                st_async32(self_h2base + doff1, v1, self_h2mbar);
                st_async32(peer_h2base + doff1, v1, peer_h2mbar);
            }

            // GEMM3 cached-weight preload for q=0,1 (constant data; hides the wait exit)
            unsigned long long pw0, pw1, pw2, pw3;
            lds_v2u64(wcb,          pw0, pw1);   // q=0
            lds_v2u64(wcb + 4096u,  pw2, pw3);   // q=1

            mbar_wait(my_h2mbar, ph);   // ALL h2 rows arrived (acquire)

            // GEMM3: thread owns n0=2tid, n0+1 (local), 4 rows; K=128 = 64 q
            unsigned long long a00 = 0, a01 = 0, a10 = 0, a11 = 0;
            unsigned long long a20 = 0, a21 = 0, a30 = 0, a31 = 0;
            #define G3_STEP(HX, HY, W00, W01, W10, W11, R0, R1)                       \
                {                                                                     \
                    R0 = fma2(HX, W00, R0); R0 = fma2(HY, W10, R0);                   \
                    R1 = fma2(HX, W01, R1); R1 = fma2(HY, W11, R1);                   \
                }
            {   // q = 0,1 using preloaded weights (same FP order as before)
                unsigned long long h0x, h0y, h1x, h1y, h2x, h2y, h3x, h3y;
                lds_v2u64(h2b,          h0x, h0y);
                lds_v2u64(h2b + 512u,   h1x, h1y);
                lds_v2u64(h2b + 1024u,  h2x, h2y);
                lds_v2u64(h2b + 1536u,  h3x, h3y);
                G3_STEP(h0x, h0y, pw0, pw1, pw2, pw3, a00, a01)
                G3_STEP(h1x, h1y, pw0, pw1, pw2, pw3, a10, a11)
                G3_STEP(h2x, h2y, pw0, pw1, pw2, pw3, a20, a21)
                G3_STEP(h3x, h3y, pw0, pw1, pw2, pw3, a30, a31)
            }
            #define G3_CACHED(Q0, Q1)                                                 \
                {                                                                     \
                    _Pragma("unroll")                                                 \
                    for (int q = (Q0); q < (Q1); q += 2) {                            \
                        unsigned long long w00, w01, w10, w11;                        \
                        lds_v2u64(wcb + (unsigned)q * 4096u, w00, w01);               \
                        lds_v2u64(wcb + (unsigned)(q + 1) * 4096u, w10, w11);         \
                        unsigned long long h0x, h0y, h1x, h1y, h2x, h2y, h3x, h3y;    \
                        lds_v2u64(h2b +           (unsigned)q * 8u, h0x, h0y);        \
                        lds_v2u64(h2b + 512u  +   (unsigned)q * 8u, h1x, h1y);        \
                        lds_v2u64(h2b + 1024u +   (unsigned)q * 8u, h2x, h2y);        \
                        lds_v2u64(h2b + 1536u +   (unsigned)q * 8u, h3x, h3y);        \
                        G3_STEP(h0x, h0y, w00, w01, w10, w11, a00, a01)               \
                        G3_STEP(h1x, h1y, w00, w01, w10, w11, a10, a11)               \
                        G3_STEP(h2x, h2y, w00, w01, w10, w11, a20, a21)               \
                        G3_STEP(h3x, h3y, w00, w01, w10, w11, a30, a31)               \
                    }                                                                 \
                }
            #define G3_CONSUME(WV, B)                                                 \
                {                                                                     \
                    _Pragma("unroll")                                                 \
                    for (int jj = 0; jj < 2; ++jj) {                                  \
                        int q = QC + 4 * (B) + 2 * jj;                                \
                        unsigned long long h0x, h0y, h1x, h1y, h2x, h2y, h3x, h3y;    \
                        lds_v2u64(h2b +           (unsigned)q * 8u, h0x, h0y);        \
                        lds_v2u64(h2b + 512u  +   (unsigned)q * 8u, h1x, h1y);        \
                        lds_v2u64(h2b + 1024u +   (unsigned)q * 8u, h2x, h2y);        \
                        lds_v2u64(h2b + 1536u +   (unsigned)q * 8u, h3x, h3y);        \
                        unsigned long long w00 = (WV)[4 * jj],     w01 = (WV)[4 * jj + 1]; \
                        unsigned long long w10 = (WV)[4 * jj + 2], w11 = (WV)[4 * jj + 3]; \
                        G3_STEP(h0x, h0y, w00, w01, w10, w11, a00, a01)               \
                        G3_STEP(h1x, h1y, w00, w01, w10, w11, a10, a11)               \
                        G3_STEP(h2x, h2y, w00, w01, w10, w11, a20, a21)               \
                        G3_STEP(h3x, h3y, w00, w01, w10, w11, a30, a31)               \
                    }                                                                 \
                }
            // schedule: 7 streamed batches (q=36..63), pipeline depth 2
            G3_CACHED(2, 18)
            G3_CONSUME(wvA, 0)  G3_ISSUE(wvA, 2)
            G3_CACHED(18, QC)
            G3_CONSUME(wvB, 1)  G3_ISSUE(wvB, 3)
            G3_CONSUME(wvA, 2)  G3_ISSUE(wvA, 4)
            G3_CONSUME(wvB, 3)  G3_ISSUE(wvB, 5)
            G3_CONSUME(wvA, 4)  G3_ISSUE(wvA, 6)
            G3_CONSUME(wvB, 5)
            G3_CONSUME(wvA, 6)

            // epilogue: fold k-parity, dx computed inline, tanh, einsum partial,
            // 8-lane reduce; ks goes out ONLY via st.async -> no S4
            float z0 = sm.bf3loc[2 * tid], z1 = sm.bf3loc[2 * tid + 1];
            float fr = cC[j] * h;
            float kv[4];
            {
                unsigned long long aa0[4] = {a00, a10, a20, a30};
                unsigned long long aa1[4] = {a01, a11, a21, a31};
                #pragma unroll
                for (int b = 0; b < 4; ++b) {
                    float2 cb = lds_f2(cb_a + (unsigned)b * 64u);
                    float2 cc = lds_f2(cc_a + (unsigned)b * 64u);
                    float2 cd = lds_f2(cd_a + (unsigned)b * 64u);
                    float dx0 = cb.x + fr * (2.0f * cc.x + 3.0f * fr * cd.x);
                    float dx1 = cb.y + fr * (2.0f * cc.y + 3.0f * fr * cd.y);
                    float2 f0 = u2f(aa0[b]);
                    float2 f1 = u2f(aa1[b]);
                    float v0 = tanh_fast(f0.x + f0.y + z0);
                    float v1 = tanh_fast(f1.x + f1.y + z1);
                    float p = v0 * dx0 + v1 * dx1;
                    p += __shfl_xor_sync(0xffffffffu, p, 1);
                    p += __shfl_xor_sync(0xffffffffu, p, 2);
                    p += __shfl_xor_sync(0xffffffffu, p, 4);
                    kv[b] = p;
                }
            }
            if (writer) {
                #pragma unroll
                for (int b = 0; b < 4; ++b) {
                    unsigned doff = (unsigned)(((j * 4 + b) * 64) + s_g) * 4u;
                    st_async32(self_ksbase + doff, kv[b], self_ksmbar);
                    st_async32(peer_ksbase + doff, kv[b], peer_ksmbar);
                }
            }
            mbar_wait(my_ksmbar, ph);  // full ks stage row set arrived (acquire)
            ph ^= 1;
        }

        {  // y += h * sum_j B_SOL[j] * ks[j]
            int b = tid >> 6, s = tid & 63;
            float sum = 0.0f;
            #pragma unroll
            for (int j = 0; j < 6; ++j) sum += cBw[j] * sm.ks[j][b][s];
            sm.y[b][s] += h * sum;
        }
        __syncthreads();  // S5

        if (tid < 16) {  // out[:, t+1, :] for 2 local rows
            int bl = tid >> 3, o = tid & 7;
            int row = (int)rank * 2 + bl;
            float acc = br[o];
            #pragma unroll 8
            for (int s2 = 0; s2 < 64; ++s2) acc += sm.y[row][s2] * Wr[o * 64 + s2];
            out[((b0g + row) * 64 + (t + 1)) * 8 + o] = acc;
        }
    }
}

extern "C" void kernel_launch(void* const* d_in, const int* in_sizes, int n_in,
                              void* d_out, int out_size) {
    const float* ts      = (const float*)d_in[0];
    const float* coeff_d = (const float*)d_in[1];
    const float* coeff_c = (const float*)d_in[2];
    const float* coeff_b = (const float*)d_in[3];
    const float* coeff_a = (const float*)d_in[4];
    const float* Wi1 = (const float*)d_in[5];
    const float* bi1 = (const float*)d_in[6];
    const float* Wi2 = (const float*)d_in[7];
    const float* bi2 = (const float*)d_in[8];
    const float* Wf1 = (const float*)d_in[9];
    const float* bf1 = (const float*)d_in[10];
    const float* Wf2 = (const float*)d_in[11];
    const float* bf2 = (const float*)d_in[12];
    const float* Wf3 = (const float*)d_in[13];
    const float* bf3 = (const float*)d_in[14];
    const float* Wr  = (const float*)d_in[15];
    const float* br  = (const float*)d_in[16];
    float* out = (float*)d_out;

    cudaFuncSetAttribute(cde_kernel, cudaFuncAttributeMaxDynamicSharedMemorySize,
                         (int)sizeof(Smem));

    prep_kernel<<<512, PREPT>>>(Wf3);
    cde_kernel<<<128, NTHR, sizeof(Smem)>>>(ts, coeff_d, coeff_c, coeff_b, coeff_a,
                                            Wi1, bi1, Wi2, bi2, Wf1, bf1, Wf2, bf2,
                                            bf3, Wr, br, out);
}